// round 1
// baseline (speedup 1.0000x reference)
#include <cuda_runtime.h>
#include <math.h>

#define N_OBJ 2048
#define FDIM  2048
#define HDIM  1024
#define G6    6144   // 6*HDIM
#define KCAT  2048   // 2*HDIM

// ---------------- scratch (static device globals; no allocation) -------------
__device__ float g_XG[(size_t)N_OBJ * G6];        // x-gates  [2048,6144]
__device__ float g_PX[(size_t)N_OBJ * HDIM];      // px       [2048,1024]
__device__ float g_Wcat[(size_t)G6 * KCAT];       // [Wl | Wr] [6144,2048]
__device__ float g_biaslr[G6];                    // b_l + b_r
__device__ float g_C[(size_t)(N_OBJ + 1) * HDIM]; // cell table (+ zero row)
__device__ float g_H[(size_t)(N_OBJ + 1) * HDIM]; // hidden table (+ zero row)
__device__ float g_Gh[(size_t)512 * G6];          // per-level h-gates scratch

// ---------------- prep: Wcat = [Wl|Wr], biaslr, zero sentinel rows -----------
__global__ void prep_kernel(const float* __restrict__ wl, const float* __restrict__ wr,
                            const float* __restrict__ bl, const float* __restrict__ br)
{
    int idx = blockIdx.x * 256 + threadIdx.x;          // over G6*KCAT/4 float4s
    int j  = idx >> 9;                                  // KCAT/4 = 512
    int k4 = (idx & 511) * 4;
    float4 v;
    if (k4 < HDIM) v = *(const float4*)(wl + (size_t)j * HDIM + k4);
    else           v = *(const float4*)(wr + (size_t)j * HDIM + (k4 - HDIM));
    ((float4*)g_Wcat)[idx] = v;
    if (idx < G6) g_biaslr[idx] = bl[idx] + br[idx];
    if (idx < HDIM) {
        g_C[(size_t)N_OBJ * HDIM + idx] = 0.f;
        g_H[(size_t)N_OBJ * HDIM + idx] = 0.f;
    }
}

// ---------------- generic tiled GEMM: C[M,N] = A[M,K] @ B[N,K]^T (+bias) -----
// BN=128, BK=8, 256 threads. BM templated (128 for big, 32 for medium levels).
template <int BM>
__global__ __launch_bounds__(256) void gemm_tn(
    const float* __restrict__ A, const float* __restrict__ B,
    const float* __restrict__ bias, float* __restrict__ C,
    int M, int N, int K)
{
    constexpr int BN = 128, BK = 8, RP = BM / 16;
    __shared__ float As[BK][BM];
    __shared__ float Bs[BK][BN];
    const int tid  = threadIdx.x;
    const int row0 = blockIdx.y * BM;
    const int col0 = blockIdx.x * BN;
    const int tr = tid >> 4, tc = tid & 15;

    float acc[RP][8];
#pragma unroll
    for (int i = 0; i < RP; i++)
#pragma unroll
        for (int j = 0; j < 8; j++) acc[i][j] = 0.f;

    const int ar = tid >> 1, ac = (tid & 1) * 4;   // A loader (BM*2 threads used)
    const int br = tid >> 1, bc = (tid & 1) * 4;   // B loader (all 256)

    for (int k0 = 0; k0 < K; k0 += BK) {
        if (BM == 128 || tid < BM * 2) {
            int r = row0 + ar;
            float4 v = make_float4(0.f, 0.f, 0.f, 0.f);
            if (r < M) v = *(const float4*)(A + (size_t)r * K + k0 + ac);
            As[ac + 0][ar] = v.x; As[ac + 1][ar] = v.y;
            As[ac + 2][ar] = v.z; As[ac + 3][ar] = v.w;
        }
        {
            float4 v = *(const float4*)(B + (size_t)(col0 + br) * K + k0 + bc);
            Bs[bc + 0][br] = v.x; Bs[bc + 1][br] = v.y;
            Bs[bc + 2][br] = v.z; Bs[bc + 3][br] = v.w;
        }
        __syncthreads();
#pragma unroll
        for (int k = 0; k < BK; k++) {
            float a[RP], b[8];
#pragma unroll
            for (int i = 0; i < RP; i++) a[i] = As[k][tr * RP + i];
#pragma unroll
            for (int j = 0; j < 8; j++) b[j] = Bs[k][tc * 8 + j];
#pragma unroll
            for (int i = 0; i < RP; i++)
#pragma unroll
                for (int j = 0; j < 8; j++) acc[i][j] += a[i] * b[j];
        }
        __syncthreads();
    }

#pragma unroll
    for (int i = 0; i < RP; i++) {
        int r = row0 + tr * RP + i;
        if (r < M) {
            float* crow = C + (size_t)r * N + col0 + tc * 8;
#pragma unroll
            for (int j = 0; j < 8; j++) {
                float v = acc[i][j];
                if (bias) v += bias[col0 + tc * 8 + j];
                crow[j] = v;
            }
        }
    }
}

// ---------------- tiny-M GEMM (M<=16): one warp per output column n ---------
__global__ void gemm_small(const float* __restrict__ A, const float* __restrict__ B,
                           float* __restrict__ C, int M, int N, int K)
{
    int warp = threadIdx.x >> 5, lane = threadIdx.x & 31;
    int n = blockIdx.x * 8 + warp;
    if (n >= N) return;
    float acc[16];
#pragma unroll
    for (int m = 0; m < 16; m++) acc[m] = 0.f;
    const float* Brow = B + (size_t)n * K;
    for (int k = lane * 4; k < K; k += 128) {
        float4 bv = *(const float4*)(Brow + k);
#pragma unroll
        for (int m = 0; m < 16; m++) {
            if (m < M) {
                float4 av = *(const float4*)(A + (size_t)m * K + k);
                acc[m] += av.x * bv.x + av.y * bv.y + av.z * bv.z + av.w * bv.w;
            }
        }
    }
#pragma unroll
    for (int m = 0; m < 16; m++) {
        if (m < M) {
            float v = acc[m];
#pragma unroll
            for (int off = 16; off; off >>= 1) v += __shfl_xor_sync(~0u, v, off);
            if (lane == 0) C[(size_t)m * N + n] = v;
        }
    }
}

// ---------------- pointwise LSTM cell for one wavefront ----------------------
__device__ __forceinline__ float sigm(float x) { return 1.f / (1.f + expf(-x)); }

__global__ void pointwise(int s, int M, const float* __restrict__ Gh)
{
    int idx = blockIdx.x * blockDim.x + threadIdx.x;
    if (idx >= M * HDIM) return;
    int m = idx >> 10;
    int j = idx & (HDIM - 1);
    int n = s + m;

    const float* xg = g_XG + (size_t)n * G6;
    const float* gh = Gh ? (Gh + (size_t)m * G6) : nullptr;
    float g[6];
#pragma unroll
    for (int t = 0; t < 6; t++) {
        int o = t * HDIM + j;
        g[t] = xg[o] + g_biaslr[o] + (gh ? gh[o] : 0.f);
    }
    float ig = sigm(g[0]), og = sigm(g[1]);
    float fl = sigm(g[2]), fr = sigm(g[3]);
    float u  = tanhf(g[4]), rr = sigm(g[5]);

    int l = 2 * n + 1; if (l > N_OBJ) l = N_OBJ;   // sentinel row = zeros
    int r = 2 * n + 2; if (r > N_OBJ) r = N_OBJ;

    float c = ig * u + fl * g_C[(size_t)l * HDIM + j] + fr * g_C[(size_t)r * HDIM + j];
    float h = og * tanhf(c);
    float hf = rr * h + (1.f - rr) * g_PX[(size_t)n * HDIM + j];

    g_C[(size_t)n * HDIM + j] = c;
    g_H[(size_t)n * HDIM + j] = hf;
}

// ---------------- final copy: H table rows 0..2047 -> d_out ------------------
__global__ void copyout(float* __restrict__ out)
{
    int idx = blockIdx.x * 256 + threadIdx.x;   // over 2048*1024/4 float4s
    ((float4*)out)[idx] = ((const float4*)g_H)[idx];
}

// ---------------- launcher ---------------------------------------------------
extern "C" void kernel_launch(void* const* d_in, const int* in_sizes, int n_in,
                              void* d_out, int out_size)
{
    const float* features = (const float*)d_in[0];
    const float* w_iox    = (const float*)d_in[1];
    const float* b_iox    = (const float*)d_in[2];
    const float* w_l      = (const float*)d_in[3];
    const float* b_l      = (const float*)d_in[4];
    const float* w_r      = (const float*)d_in[5];
    const float* b_r      = (const float*)d_in[6];
    const float* w_px     = (const float*)d_in[7];
    const float* b_px     = (const float*)d_in[8];
    // d_in[9], d_in[10] (child indices) are implied by heap layout; unused.

    float *XG, *PX, *Wcat, *Gh, *Htab;
    cudaGetSymbolAddress((void**)&XG,   g_XG);
    cudaGetSymbolAddress((void**)&PX,   g_PX);
    cudaGetSymbolAddress((void**)&Wcat, g_Wcat);
    cudaGetSymbolAddress((void**)&Gh,   g_Gh);
    cudaGetSymbolAddress((void**)&Htab, g_H);

    // prep: Wcat, biaslr, sentinel zero rows
    prep_kernel<<<(G6 * KCAT / 4) / 256, 256>>>(w_l, w_r, b_l, b_r);

    // phase A: x-gates and px (fully batched)
    gemm_tn<128><<<dim3(G6 / 128,   N_OBJ / 128), 256>>>(features, w_iox, b_iox, XG, N_OBJ, G6,   FDIM);
    gemm_tn<128><<<dim3(HDIM / 128, N_OBJ / 128), 256>>>(features, w_px,  b_px,  PX, N_OBJ, HDIM, FDIM);

    // leaves: nodes 1024..2047, gates = XG + (b_l + b_r)
    pointwise<<<(1024 * HDIM + 255) / 256, 256>>>(1024, 1024, nullptr);

    // internal wavefronts, deepest first. Children of [s, s+M) are contiguous
    // H rows [2s+1, 2s+1+2M) -> plain GEMM with A = &H[(2s+1)*HDIM], K = 2048.
    struct Lv { int s, M; };
    const Lv lvs[11] = { {1023, 1}, {511, 512}, {255, 256}, {127, 128}, {63, 64},
                         {31, 32}, {15, 16}, {7, 8}, {3, 4}, {1, 2}, {0, 1} };
    for (int li = 0; li < 11; li++) {
        int s = lvs[li].s, M = lvs[li].M;
        const float* A = Htab + (size_t)(2 * s + 1) * HDIM;
        if (M >= 256) {
            gemm_tn<128><<<dim3(G6 / 128, (M + 127) / 128), 256>>>(A, Wcat, nullptr, Gh, M, G6, KCAT);
        } else if (M >= 32) {
            gemm_tn<32><<<dim3(G6 / 128, (M + 31) / 32), 256>>>(A, Wcat, nullptr, Gh, M, G6, KCAT);
        } else {
            gemm_small<<<G6 / 8, 256>>>(A, Wcat, Gh, M, G6, KCAT);
        }
        pointwise<<<(M * HDIM + 255) / 256, 256>>>(s, M, Gh);
    }

    copyout<<<(N_OBJ * HDIM / 4) / 256, 256>>>((float*)d_out);
}

// round 2
// speedup vs baseline: 1.1007x; 1.1007x over previous
#include <cuda_runtime.h>
#include <math.h>
#include <stdint.h>

#define N_OBJ 2048
#define FDIM  2048
#define HDIM  1024
#define G6    6144   // 6*HDIM
#define KCAT  2048   // 2*HDIM

// ---------------- scratch (static device globals; no allocation) -------------
__device__ float g_XG[(size_t)N_OBJ * G6];        // x-gates  [2048,6144]
__device__ float g_PX[(size_t)N_OBJ * HDIM];      // px       [2048,1024]
__device__ float g_Wcat[(size_t)G6 * KCAT];       // [Wl | Wr] fp32 (tiny-M path)
__device__ float g_biaslr[G6];                    // b_l + b_r
__device__ float g_C[(size_t)(N_OBJ + 1) * HDIM]; // cell table (+ zero row)
__device__ float g_H[(size_t)(N_OBJ + 1) * HDIM]; // hidden table (+ zero row)
__device__ float g_Gh[(size_t)512 * G6];          // per-level h-gates scratch

// tf32 split operands (bit patterns, fp32-compatible with low 13 bits zero)
__device__ uint32_t g_Wcat_hi[(size_t)G6 * KCAT],  g_Wcat_lo[(size_t)G6 * KCAT];
__device__ uint32_t g_F_hi[(size_t)N_OBJ * FDIM],  g_F_lo[(size_t)N_OBJ * FDIM];
__device__ uint32_t g_Wx_hi[(size_t)G6 * FDIM],    g_Wx_lo[(size_t)G6 * FDIM];
__device__ uint32_t g_Wp_hi[(size_t)HDIM * FDIM],  g_Wp_lo[(size_t)HDIM * FDIM];
__device__ uint32_t g_Hhi[(size_t)(N_OBJ + 1) * HDIM], g_Hlo[(size_t)(N_OBJ + 1) * HDIM];

// ---------------- tf32 helpers ----------------------------------------------
__device__ __forceinline__ uint32_t f2tf(float x) {
    uint32_t r; asm("cvt.rna.tf32.f32 %0, %1;" : "=r"(r) : "f"(x)); return r;
}
__device__ __forceinline__ void tf32_split(float x, uint32_t& hi, uint32_t& lo) {
    hi = f2tf(x);
    lo = f2tf(x - __uint_as_float(hi));
}

// ---------------- split kernel: fp32 -> (hi, lo) tf32 ------------------------
__global__ void split_kernel(const float* __restrict__ src,
                             uint32_t* __restrict__ hi, uint32_t* __restrict__ lo, int n)
{
    int i = blockIdx.x * 256 + threadIdx.x;
    if (i < n) tf32_split(src[i], hi[i], lo[i]);
}

// ---------------- prep: Wcat fp32 + split, biaslr, sentinel rows -------------
__global__ void prep_kernel(const float* __restrict__ wl, const float* __restrict__ wr,
                            const float* __restrict__ bl, const float* __restrict__ br)
{
    int idx = blockIdx.x * 256 + threadIdx.x;   // over G6*KCAT
    int j = idx >> 11;          // / KCAT
    int k = idx & (KCAT - 1);
    float w = (k < HDIM) ? wl[(size_t)j * HDIM + k] : wr[(size_t)j * HDIM + (k - HDIM)];
    g_Wcat[idx] = w;
    tf32_split(w, g_Wcat_hi[idx], g_Wcat_lo[idx]);
    if (idx < G6) g_biaslr[idx] = bl[idx] + br[idx];
    if (idx < HDIM) {
        size_t s = (size_t)N_OBJ * HDIM + idx;
        g_C[s] = 0.f; g_H[s] = 0.f; g_Hhi[s] = 0u; g_Hlo[s] = 0u;
    }
}

// ---------------- mma.sync tf32 wrapper --------------------------------------
__device__ __forceinline__ void mma_tf32(float* c, const uint32_t* a, const uint32_t* b)
{
    asm volatile(
        "mma.sync.aligned.m16n8k8.row.col.f32.tf32.tf32.f32 "
        "{%0,%1,%2,%3}, {%4,%5,%6,%7}, {%8,%9}, {%0,%1,%2,%3};"
        : "+f"(c[0]), "+f"(c[1]), "+f"(c[2]), "+f"(c[3])
        : "r"(a[0]), "r"(a[1]), "r"(a[2]), "r"(a[3]), "r"(b[0]), "r"(b[1]));
}

// ---------------- tensor-core GEMM: C[M,N] = A @ B^T (+bias), 3xTF32 ---------
// A, B given as pre-split tf32 hi/lo. BN=128 fixed, BK=16, 256 threads.
// BM=128: 8 warps as 2x4, warp tile 64x32. BM=32: 1x8, warp tile 32x16.
template <int BM>
__global__ __launch_bounds__(256) void gemm_mma(
    const uint32_t* __restrict__ Ahi, const uint32_t* __restrict__ Alo,
    const uint32_t* __restrict__ Bhi, const uint32_t* __restrict__ Blo,
    const float* __restrict__ bias, float* __restrict__ C,
    int M, int N, int K)
{
    constexpr int BN = 128, BK = 16;
    constexpr int LDA = BM + 8;      // smem stride -> conflict-free frag loads
    constexpr int LDB = BN + 8;
    constexpr int WR = (BM == 128) ? 2 : 1;   // warp rows
    constexpr int WC = 8 / WR;                // warp cols
    constexpr int WM = BM / WR;               // 64 / 32
    constexpr int WN = BN / WC;               // 32 / 16
    constexpr int MF = WM / 16;               // m16 frags per warp: 4 / 2
    constexpr int NF = WN / 8;                // n8  frags per warp: 4 / 2

    __shared__ uint32_t As[2][BK][LDA];   // [hi/lo][k][m]
    __shared__ uint32_t Bs[2][BK][LDB];   // [hi/lo][k][n]

    const int tid  = threadIdx.x;
    const int lane = tid & 31;
    const int warp = tid >> 5;
    const int wr_  = warp / WC;
    const int wc_  = warp % WC;
    const int row0 = blockIdx.y * BM;
    const int col0 = blockIdx.x * BN;
    const int tr = lane >> 2, tk = lane & 3;

    float acc[MF][NF][4];
#pragma unroll
    for (int i = 0; i < MF; i++)
#pragma unroll
        for (int j = 0; j < NF; j++)
#pragma unroll
            for (int t = 0; t < 4; t++) acc[i][j][t] = 0.f;

    for (int k0 = 0; k0 < K; k0 += BK) {
        // ---- load A tile (BM x 16) hi+lo, transposed into As[k][m] ----
        for (int i = tid; i < BM * 4; i += 256) {
            int row = i >> 2;
            int c4  = (i & 3) * 4;
            int gr  = row0 + row;
            uint4 vh = make_uint4(0u, 0u, 0u, 0u), vl = vh;
            if (gr < M) {
                vh = *(const uint4*)(Ahi + (size_t)gr * K + k0 + c4);
                vl = *(const uint4*)(Alo + (size_t)gr * K + k0 + c4);
            }
            As[0][c4 + 0][row] = vh.x; As[0][c4 + 1][row] = vh.y;
            As[0][c4 + 2][row] = vh.z; As[0][c4 + 3][row] = vh.w;
            As[1][c4 + 0][row] = vl.x; As[1][c4 + 1][row] = vl.y;
            As[1][c4 + 2][row] = vl.z; As[1][c4 + 3][row] = vl.w;
        }
        // ---- load B tile (128 x 16) hi+lo, transposed into Bs[k][n] ----
        for (int i = tid; i < BN * 4; i += 256) {
            int row = i >> 2;
            int c4  = (i & 3) * 4;
            int gn  = col0 + row;
            uint4 vh = *(const uint4*)(Bhi + (size_t)gn * K + k0 + c4);
            uint4 vl = *(const uint4*)(Blo + (size_t)gn * K + k0 + c4);
            Bs[0][c4 + 0][row] = vh.x; Bs[0][c4 + 1][row] = vh.y;
            Bs[0][c4 + 2][row] = vh.z; Bs[0][c4 + 3][row] = vh.w;
            Bs[1][c4 + 0][row] = vl.x; Bs[1][c4 + 1][row] = vl.y;
            Bs[1][c4 + 2][row] = vl.z; Bs[1][c4 + 3][row] = vl.w;
        }
        __syncthreads();

#pragma unroll
        for (int kk = 0; kk < BK; kk += 8) {
            uint32_t afh[MF][4], afl[MF][4], bfh[NF][2], bfl[NF][2];
#pragma unroll
            for (int mf = 0; mf < MF; mf++) {
                int m = wr_ * WM + mf * 16 + tr;
                afh[mf][0] = As[0][kk + tk][m];     afh[mf][1] = As[0][kk + tk][m + 8];
                afh[mf][2] = As[0][kk + tk + 4][m]; afh[mf][3] = As[0][kk + tk + 4][m + 8];
                afl[mf][0] = As[1][kk + tk][m];     afl[mf][1] = As[1][kk + tk][m + 8];
                afl[mf][2] = As[1][kk + tk + 4][m]; afl[mf][3] = As[1][kk + tk + 4][m + 8];
            }
#pragma unroll
            for (int nf = 0; nf < NF; nf++) {
                int n = wc_ * WN + nf * 8 + tr;
                bfh[nf][0] = Bs[0][kk + tk][n]; bfh[nf][1] = Bs[0][kk + tk + 4][n];
                bfl[nf][0] = Bs[1][kk + tk][n]; bfl[nf][1] = Bs[1][kk + tk + 4][n];
            }
            // 3xTF32: hi*hi + hi*lo + lo*hi
#pragma unroll
            for (int mf = 0; mf < MF; mf++)
#pragma unroll
                for (int nf = 0; nf < NF; nf++) {
                    mma_tf32(acc[mf][nf], afh[mf], bfh[nf]);
                    mma_tf32(acc[mf][nf], afh[mf], bfl[nf]);
                    mma_tf32(acc[mf][nf], afl[mf], bfh[nf]);
                }
        }
        __syncthreads();
    }

    // ---- epilogue ----
#pragma unroll
    for (int mf = 0; mf < MF; mf++) {
#pragma unroll
        for (int nf = 0; nf < NF; nf++) {
            int r  = row0 + wr_ * WM + mf * 16 + tr;
            int cb = col0 + wc_ * WN + nf * 8 + (lane & 3) * 2;
            float b0 = bias ? bias[cb] : 0.f;
            float b1 = bias ? bias[cb + 1] : 0.f;
            if (r < M) {
                C[(size_t)r * N + cb]     = acc[mf][nf][0] + b0;
                C[(size_t)r * N + cb + 1] = acc[mf][nf][1] + b1;
            }
            if (r + 8 < M) {
                C[(size_t)(r + 8) * N + cb]     = acc[mf][nf][2] + b0;
                C[(size_t)(r + 8) * N + cb + 1] = acc[mf][nf][3] + b1;
            }
        }
    }
}

// ---------------- tiny-M GEMM (M<=16): one warp per output column n ---------
__global__ void gemm_small(const float* __restrict__ A, const float* __restrict__ B,
                           float* __restrict__ C, int M, int N, int K)
{
    int warp = threadIdx.x >> 5, lane = threadIdx.x & 31;
    int n = blockIdx.x * 8 + warp;
    if (n >= N) return;
    float acc[16];
#pragma unroll
    for (int m = 0; m < 16; m++) acc[m] = 0.f;
    const float* Brow = B + (size_t)n * K;
    for (int k = lane * 4; k < K; k += 128) {
        float4 bv = *(const float4*)(Brow + k);
#pragma unroll
        for (int m = 0; m < 16; m++) {
            if (m < M) {
                float4 av = *(const float4*)(A + (size_t)m * K + k);
                acc[m] += av.x * bv.x + av.y * bv.y + av.z * bv.z + av.w * bv.w;
            }
        }
    }
#pragma unroll
    for (int m = 0; m < 16; m++) {
        if (m < M) {
            float v = acc[m];
#pragma unroll
            for (int off = 16; off; off >>= 1) v += __shfl_xor_sync(~0u, v, off);
            if (lane == 0) C[(size_t)m * N + n] = v;
        }
    }
}

// ---------------- pointwise LSTM cell for one wavefront ----------------------
__device__ __forceinline__ float sigm(float x) { return 1.f / (1.f + expf(-x)); }

__global__ void pointwise(int s, int M, const float* __restrict__ Gh)
{
    int idx = blockIdx.x * blockDim.x + threadIdx.x;
    if (idx >= M * HDIM) return;
    int m = idx >> 10;
    int j = idx & (HDIM - 1);
    int n = s + m;

    const float* xg = g_XG + (size_t)n * G6;
    const float* gh = Gh ? (Gh + (size_t)m * G6) : nullptr;
    float g[6];
#pragma unroll
    for (int t = 0; t < 6; t++) {
        int o = t * HDIM + j;
        g[t] = xg[o] + g_biaslr[o] + (gh ? gh[o] : 0.f);
    }
    float ig = sigm(g[0]), og = sigm(g[1]);
    float fl = sigm(g[2]), fr = sigm(g[3]);
    float u  = tanhf(g[4]), rr = sigm(g[5]);

    int l = 2 * n + 1; if (l > N_OBJ) l = N_OBJ;   // sentinel row = zeros
    int r = 2 * n + 2; if (r > N_OBJ) r = N_OBJ;

    float c = ig * u + fl * g_C[(size_t)l * HDIM + j] + fr * g_C[(size_t)r * HDIM + j];
    float h = og * tanhf(c);
    float hf = rr * h + (1.f - rr) * g_PX[(size_t)n * HDIM + j];

    size_t o = (size_t)n * HDIM + j;
    g_C[o] = c;
    g_H[o] = hf;
    tf32_split(hf, g_Hhi[o], g_Hlo[o]);
}

// ---------------- final copy: H table rows 0..2047 -> d_out ------------------
__global__ void copyout(float* __restrict__ out)
{
    int idx = blockIdx.x * 256 + threadIdx.x;   // over 2048*1024/4 float4s
    ((float4*)out)[idx] = ((const float4*)g_H)[idx];
}

// ---------------- launcher ---------------------------------------------------
extern "C" void kernel_launch(void* const* d_in, const int* in_sizes, int n_in,
                              void* d_out, int out_size)
{
    const float* features = (const float*)d_in[0];
    const float* w_iox    = (const float*)d_in[1];
    const float* b_iox    = (const float*)d_in[2];
    const float* w_l      = (const float*)d_in[3];
    const float* b_l      = (const float*)d_in[4];
    const float* w_r      = (const float*)d_in[5];
    const float* b_r      = (const float*)d_in[6];
    const float* w_px     = (const float*)d_in[7];
    const float* b_px     = (const float*)d_in[8];
    // d_in[9], d_in[10] (child indices) implied by heap layout; unused.

    float *XG, *PX, *Wcat, *Gh, *Htab;
    uint32_t *Fh, *Fl, *Wxh, *Wxl, *Wph, *Wpl, *Wch, *Wcl, *Hh, *Hl;
    cudaGetSymbolAddress((void**)&XG,   g_XG);
    cudaGetSymbolAddress((void**)&PX,   g_PX);
    cudaGetSymbolAddress((void**)&Wcat, g_Wcat);
    cudaGetSymbolAddress((void**)&Gh,   g_Gh);
    cudaGetSymbolAddress((void**)&Htab, g_H);
    cudaGetSymbolAddress((void**)&Fh,   g_F_hi);   cudaGetSymbolAddress((void**)&Fl, g_F_lo);
    cudaGetSymbolAddress((void**)&Wxh,  g_Wx_hi);  cudaGetSymbolAddress((void**)&Wxl, g_Wx_lo);
    cudaGetSymbolAddress((void**)&Wph,  g_Wp_hi);  cudaGetSymbolAddress((void**)&Wpl, g_Wp_lo);
    cudaGetSymbolAddress((void**)&Wch,  g_Wcat_hi);cudaGetSymbolAddress((void**)&Wcl, g_Wcat_lo);
    cudaGetSymbolAddress((void**)&Hh,   g_Hhi);    cudaGetSymbolAddress((void**)&Hl,  g_Hlo);

    // prep: Wcat fp32 + tf32 split, biaslr, sentinel zero rows
    prep_kernel<<<(G6 * KCAT) / 256, 256>>>(w_l, w_r, b_l, b_r);
    split_kernel<<<(N_OBJ * FDIM) / 256, 256>>>(features, Fh, Fl, N_OBJ * FDIM);
    split_kernel<<<(G6 * FDIM) / 256, 256>>>(w_iox, Wxh, Wxl, G6 * FDIM);
    split_kernel<<<(HDIM * FDIM) / 256, 256>>>(w_px, Wph, Wpl, HDIM * FDIM);

    // phase A: x-gates and px (tensor-core 3xTF32)
    gemm_mma<128><<<dim3(G6 / 128,   N_OBJ / 128), 256>>>(Fh, Fl, Wxh, Wxl, b_iox, XG, N_OBJ, G6,   FDIM);
    gemm_mma<128><<<dim3(HDIM / 128, N_OBJ / 128), 256>>>(Fh, Fl, Wph, Wpl, b_px,  PX, N_OBJ, HDIM, FDIM);

    // leaves: nodes 1024..2047, gates = XG + (b_l + b_r)
    pointwise<<<(1024 * HDIM + 255) / 256, 256>>>(1024, 1024, nullptr);

    // internal wavefronts, deepest first. Children of [s, s+M) are contiguous
    // H rows [2s+1, 2s+1+2M) -> plain GEMM, A = &H*[(2s+1)*HDIM], K = 2048.
    struct Lv { int s, M; };
    const Lv lvs[11] = { {1023, 1}, {511, 512}, {255, 256}, {127, 128}, {63, 64},
                         {31, 32}, {15, 16}, {7, 8}, {3, 4}, {1, 2}, {0, 1} };
    for (int li = 0; li < 11; li++) {
        int s = lvs[li].s, M = lvs[li].M;
        size_t aoff = (size_t)(2 * s + 1) * HDIM;
        if (M >= 128) {
            gemm_mma<128><<<dim3(G6 / 128, (M + 127) / 128), 256>>>(
                Hh + aoff, Hl + aoff, Wch, Wcl, nullptr, Gh, M, G6, KCAT);
        } else if (M >= 32) {
            gemm_mma<32><<<dim3(G6 / 128, (M + 31) / 32), 256>>>(
                Hh + aoff, Hl + aoff, Wch, Wcl, nullptr, Gh, M, G6, KCAT);
        } else {
            gemm_small<<<G6 / 8, 256>>>(Htab + aoff, Wcat, Gh, M, G6, KCAT);
        }
        pointwise<<<(M * HDIM + 255) / 256, 256>>>(s, M, Gh);
    }

    copyout<<<(N_OBJ * HDIM / 4) / 256, 256>>>((float*)d_out);
}

// round 6
// speedup vs baseline: 1.2830x; 1.1656x over previous
#include <cuda_runtime.h>
#include <cuda_bf16.h>
#include <math.h>
#include <stdint.h>

#define N_OBJ 2048
#define FDIM  2048
#define HDIM  1024
#define G6    6144          // 6*HDIM
#define KCAT  2048          // 2*HDIM
#define NCH   384           // 6 terms * (2048/32) k-chunks

// plane strides (elements)
#define PS_F  ((size_t)N_OBJ * FDIM)
#define PS_WX ((size_t)G6 * FDIM)
#define PS_WP ((size_t)HDIM * FDIM)
#define PS_WC ((size_t)G6 * KCAT)
#define PS_H  ((size_t)(N_OBJ + 1) * HDIM)

// term tables (nibble-packed): term t -> A plane TA[t], B plane TB[t]
// TA = {0,0,1,1,0,2}, TB = {0,1,0,1,2,0}
#define TA_PACK 0x201100u
#define TB_PACK 0x021010u

// ---------------- scratch (static device globals; no allocation) -------------
__device__ float g_XG[(size_t)N_OBJ * G6];
__device__ float g_PX[(size_t)N_OBJ * HDIM];
__device__ float g_Wcat[(size_t)G6 * KCAT];          // fp32 (tiny-M path)
__device__ float g_biaslr[G6];
__device__ float g_C[(size_t)(N_OBJ + 1) * HDIM];
__device__ float g_H[(size_t)(N_OBJ + 1) * HDIM];
__device__ float g_Gh[(size_t)512 * G6];

// bf16 split planes (3 planes each: t0, t1, t2)
__device__ __nv_bfloat16 g_Fe [3 * PS_F];
__device__ __nv_bfloat16 g_Wxe[3 * PS_WX];
__device__ __nv_bfloat16 g_Wpe[3 * PS_WP];
__device__ __nv_bfloat16 g_Wce[3 * PS_WC];
__device__ __nv_bfloat16 g_He [3 * PS_H];

// ---------------- helpers ----------------------------------------------------
__device__ __forceinline__ uint32_t smem_to_u32(const void* p) {
    uint32_t a;
    asm("{ .reg .u64 t; cvta.to.shared.u64 t, %1; cvt.u32.u64 %0, t; }" : "=r"(a) : "l"(p));
    return a;
}
__device__ __forceinline__ void ldmx4(uint32_t* d, uint32_t addr) {
    asm volatile("ldmatrix.sync.aligned.m8n8.x4.shared.b16 {%0,%1,%2,%3}, [%4];"
                 : "=r"(d[0]), "=r"(d[1]), "=r"(d[2]), "=r"(d[3]) : "r"(addr));
}
__device__ __forceinline__ void mma_bf16(float* c, const uint32_t* a, const uint32_t* b) {
    asm volatile("mma.sync.aligned.m16n8k16.row.col.f32.bf16.bf16.f32 "
                 "{%0,%1,%2,%3}, {%4,%5,%6,%7}, {%8,%9}, {%0,%1,%2,%3};"
                 : "+f"(c[0]), "+f"(c[1]), "+f"(c[2]), "+f"(c[3])
                 : "r"(a[0]), "r"(a[1]), "r"(a[2]), "r"(a[3]), "r"(b[0]), "r"(b[1]));
}
__device__ __forceinline__ void cpasync16(uint32_t dst, const void* src) {
    asm volatile("cp.async.cg.shared.global [%0], [%1], 16;" :: "r"(dst), "l"(src));
}

// swizzle: 16B chunk x (0..3) within a 64B row r  ->  conflict-free for
// both cp.async stores and ldmatrix reads (even rows use banks 0-15,
// odd rows banks 16-31, 4 distinct quads per parity class).
__device__ __forceinline__ uint32_t swz(int r, int x) {
    return (uint32_t)(r * 64 + ((x ^ ((r >> 1) & 3)) << 4));
}

// ---------------- bf16 triple-split ------------------------------------------
__device__ __forceinline__ void bf16_split3(float x, __nv_bfloat16& t0,
                                            __nv_bfloat16& t1, __nv_bfloat16& t2)
{
    t0 = __float2bfloat16(x);
    float r1 = x - __bfloat162float(t0);
    t1 = __float2bfloat16(r1);
    float r2 = r1 - __bfloat162float(t1);
    t2 = __float2bfloat16(r2);
}

// expand src fp32 [total] into 3 bf16 planes (t0, t1, t2)
__global__ void expand_kernel(const float* __restrict__ src, __nv_bfloat16* __restrict__ dst,
                              size_t planeStride, int total)
{
    int i = blockIdx.x * 256 + threadIdx.x;
    if (i >= total) return;
    __nv_bfloat16 t0, t1, t2;
    bf16_split3(src[i], t0, t1, t2);
    dst[i] = t0;
    dst[planeStride + i] = t1;
    dst[2 * planeStride + i] = t2;
}

// ---------------- prep: Wcat fp32, biaslr, sentinel rows ---------------------
__global__ void prep_kernel(const float* __restrict__ wl, const float* __restrict__ wr,
                            const float* __restrict__ bl, const float* __restrict__ br)
{
    int idx = blockIdx.x * 256 + threadIdx.x;   // over G6*KCAT
    int j = idx >> 11;
    int k = idx & (KCAT - 1);
    float w = (k < HDIM) ? wl[(size_t)j * HDIM + k] : wr[(size_t)j * HDIM + (k - HDIM)];
    g_Wcat[idx] = w;
    if (idx < G6) g_biaslr[idx] = bl[idx] + br[idx];
    if (idx < HDIM) {
        size_t s = (size_t)N_OBJ * HDIM + idx;
        g_C[s] = 0.f; g_H[s] = 0.f;
        __nv_bfloat16 z = __float2bfloat16(0.f);
        g_He[s] = z; g_He[PS_H + s] = z; g_He[2 * PS_H + s] = z;
    }
}

// ---------------- bf16 mma GEMM: C = sum_t A[TA(t)] @ B[TB(t)]^T (+bias) -----
// A, B: 3 bf16 planes, row stride 2048 elems within each plane.
// BM=BN=128, BK=32, 4-stage cp.async pipeline, ldmatrix fragments.
// Chunk c (0..NCH-1): term t = c>>6, k offset = (c&63)*32.
__global__ __launch_bounds__(256, 2) void gemm_bf(
    const __nv_bfloat16* __restrict__ A, size_t psA,
    const __nv_bfloat16* __restrict__ B, size_t psB,
    const float* __restrict__ bias, float* __restrict__ C, int M, int N)
{
    extern __shared__ char smem[];
    const uint32_t sb = smem_to_u32(smem);
    const int tid = threadIdx.x, lane = tid & 31, warp = tid >> 5;
    const int wr_ = warp >> 2, wc_ = warp & 3;            // 2 x 4 warp grid
    const int row0 = blockIdx.y * 128, col0 = blockIdx.x * 128;

    // ldmatrix lane geometry
    const int lrow = ((lane >> 3) & 1) * 8 + (lane & 7);  // row within 16
    const int lcol = lane >> 4;                           // 0/1 -> k 16B chunk

    // cp.async op coords (ops o = tid and tid+256; r = o>>2, ch = o&3)
    const int r_op0 = tid >> 2,         ch0 = tid & 3;
    const int r_op1 = (tid + 256) >> 2, ch1 = tid & 3;

    float acc[4][4][4];
#pragma unroll
    for (int a = 0; a < 4; a++)
#pragma unroll
        for (int b = 0; b < 4; b++)
#pragma unroll
            for (int t = 0; t < 4; t++) acc[a][b][t] = 0.f;

    auto load_chunk = [&](int c, int st) {
        int t = c >> 6;
        size_t pa = (size_t)((TA_PACK >> (4 * t)) & 0xF) * psA;
        size_t pb = (size_t)((TB_PACK >> (4 * t)) & 0xF) * psB;
        const __nv_bfloat16* Ab = A + pa + (size_t)(c & 63) * 32;
        const __nv_bfloat16* Bb = B + pb + (size_t)(c & 63) * 32;
        uint32_t sA = sb + st * 16384, sBm = sA + 8192;
        cpasync16(sA  + swz(r_op0, ch0), Ab + (size_t)(row0 + r_op0) * 2048 + ch0 * 8);
        cpasync16(sA  + swz(r_op1, ch1), Ab + (size_t)(row0 + r_op1) * 2048 + ch1 * 8);
        cpasync16(sBm + swz(r_op0, ch0), Bb + (size_t)(col0 + r_op0) * 2048 + ch0 * 8);
        cpasync16(sBm + swz(r_op1, ch1), Bb + (size_t)(col0 + r_op1) * 2048 + ch1 * 8);
        asm volatile("cp.async.commit_group;" ::: "memory");
    };

    load_chunk(0, 0); load_chunk(1, 1); load_chunk(2, 2);

    for (int c = 0; c < NCH; c++) {
        int st = c & 3;
        // tail-correct wait: while loads are still being issued, keep 2 groups
        // in flight; in the last 3 iterations drain everything.
        if (c + 3 < NCH) {
            asm volatile("cp.async.wait_group 2;" ::: "memory");
        } else {
            asm volatile("cp.async.wait_group 0;" ::: "memory");
        }
        __syncthreads();
        if (c + 3 < NCH) load_chunk(c + 3, (c + 3) & 3);

        uint32_t sA = sb + st * 16384, sBm = sA + 8192;
#pragma unroll
        for (int kk = 0; kk < 2; kk++) {                  // two k16 steps
            uint32_t af[4][4], bq[2][4];
#pragma unroll
            for (int mf = 0; mf < 4; mf++) {
                int r = wr_ * 64 + mf * 16 + lrow;
                ldmx4(af[mf], sA + swz(r, lcol + kk * 2));
            }
#pragma unroll
            for (int bh = 0; bh < 2; bh++) {
                int r = wc_ * 32 + bh * 16 + lrow;
                ldmx4(bq[bh], sBm + swz(r, lcol + kk * 2));
            }
#pragma unroll
            for (int mf = 0; mf < 4; mf++)
#pragma unroll
                for (int nf = 0; nf < 4; nf++) {
                    uint32_t b2[2] = { bq[nf >> 1][nf & 1], bq[nf >> 1][2 + (nf & 1)] };
                    mma_bf16(acc[mf][nf], af[mf], b2);
                }
        }
    }

    // ---- epilogue ----
#pragma unroll
    for (int mf = 0; mf < 4; mf++) {
#pragma unroll
        for (int nf = 0; nf < 4; nf++) {
            int r  = row0 + wr_ * 64 + mf * 16 + (lane >> 2);
            int cb = col0 + wc_ * 32 + nf * 8 + (lane & 3) * 2;
            float b0 = bias ? bias[cb] : 0.f;
            float b1 = bias ? bias[cb + 1] : 0.f;
            if (r < M) {
                C[(size_t)r * N + cb]     = acc[mf][nf][0] + b0;
                C[(size_t)r * N + cb + 1] = acc[mf][nf][1] + b1;
            }
            if (r + 8 < M) {
                C[(size_t)(r + 8) * N + cb]     = acc[mf][nf][2] + b0;
                C[(size_t)(r + 8) * N + cb + 1] = acc[mf][nf][3] + b1;
            }
        }
    }
}

// ---------------- tiny-M GEMM (M<=16): one warp per output column n ---------
__global__ void gemm_small(const float* __restrict__ A, const float* __restrict__ B,
                           float* __restrict__ C, int M, int N, int K)
{
    int warp = threadIdx.x >> 5, lane = threadIdx.x & 31;
    int n = blockIdx.x * 8 + warp;
    if (n >= N) return;
    float acc[16];
#pragma unroll
    for (int m = 0; m < 16; m++) acc[m] = 0.f;
    const float* Brow = B + (size_t)n * K;
    for (int k = lane * 4; k < K; k += 128) {
        float4 bv = *(const float4*)(Brow + k);
#pragma unroll
        for (int m = 0; m < 16; m++) {
            if (m < M) {
                float4 av = *(const float4*)(A + (size_t)m * K + k);
                acc[m] += av.x * bv.x + av.y * bv.y + av.z * bv.z + av.w * bv.w;
            }
        }
    }
#pragma unroll
    for (int m = 0; m < 16; m++) {
        if (m < M) {
            float v = acc[m];
#pragma unroll
            for (int off = 16; off; off >>= 1) v += __shfl_xor_sync(~0u, v, off);
            if (lane == 0) C[(size_t)m * N + n] = v;
        }
    }
}

// ---------------- pointwise LSTM cell for one wavefront ----------------------
__device__ __forceinline__ float sigm(float x) { return 1.f / (1.f + expf(-x)); }

__global__ void pointwise(int s, int M, const float* __restrict__ Gh)
{
    int idx = blockIdx.x * blockDim.x + threadIdx.x;
    if (idx >= M * HDIM) return;
    int m = idx >> 10;
    int j = idx & (HDIM - 1);
    int n = s + m;

    const float* xg = g_XG + (size_t)n * G6;
    const float* gh = Gh ? (Gh + (size_t)m * G6) : nullptr;
    float g[6];
#pragma unroll
    for (int t = 0; t < 6; t++) {
        int o = t * HDIM + j;
        g[t] = xg[o] + g_biaslr[o] + (gh ? gh[o] : 0.f);
    }
    float ig = sigm(g[0]), og = sigm(g[1]);
    float fl = sigm(g[2]), fr = sigm(g[3]);
    float u  = tanhf(g[4]), rr = sigm(g[5]);

    int l = 2 * n + 1; if (l > N_OBJ) l = N_OBJ;
    int r = 2 * n + 2; if (r > N_OBJ) r = N_OBJ;

    float c = ig * u + fl * g_C[(size_t)l * HDIM + j] + fr * g_C[(size_t)r * HDIM + j];
    float h = og * tanhf(c);
    float hf = rr * h + (1.f - rr) * g_PX[(size_t)n * HDIM + j];

    size_t o = (size_t)n * HDIM + j;
    g_C[o] = c;
    g_H[o] = hf;
    __nv_bfloat16 t0, t1, t2;
    bf16_split3(hf, t0, t1, t2);
    g_He[o] = t0; g_He[PS_H + o] = t1; g_He[2 * PS_H + o] = t2;
}

// ---------------- final copy -------------------------------------------------
__global__ void copyout(float* __restrict__ out)
{
    int idx = blockIdx.x * 256 + threadIdx.x;
    ((float4*)out)[idx] = ((const float4*)g_H)[idx];
}

// ---------------- launcher ---------------------------------------------------
extern "C" void kernel_launch(void* const* d_in, const int* in_sizes, int n_in,
                              void* d_out, int out_size)
{
    const float* features = (const float*)d_in[0];
    const float* w_iox    = (const float*)d_in[1];
    const float* b_iox    = (const float*)d_in[2];
    const float* w_l      = (const float*)d_in[3];
    const float* b_l      = (const float*)d_in[4];
    const float* w_r      = (const float*)d_in[5];
    const float* b_r      = (const float*)d_in[6];
    const float* w_px     = (const float*)d_in[7];
    const float* b_px     = (const float*)d_in[8];

    float *XG, *PX, *Wcat, *Gh, *Htab;
    __nv_bfloat16 *Fe, *Wxe, *Wpe, *Wce, *He;
    cudaGetSymbolAddress((void**)&XG,   g_XG);
    cudaGetSymbolAddress((void**)&PX,   g_PX);
    cudaGetSymbolAddress((void**)&Wcat, g_Wcat);
    cudaGetSymbolAddress((void**)&Gh,   g_Gh);
    cudaGetSymbolAddress((void**)&Htab, g_H);
    cudaGetSymbolAddress((void**)&Fe,   g_Fe);
    cudaGetSymbolAddress((void**)&Wxe,  g_Wxe);
    cudaGetSymbolAddress((void**)&Wpe,  g_Wpe);
    cudaGetSymbolAddress((void**)&Wce,  g_Wce);
    cudaGetSymbolAddress((void**)&He,   g_He);

    const int SMEM_TC = 4 * 16384;
    cudaFuncSetAttribute(gemm_bf, cudaFuncAttributeMaxDynamicSharedMemorySize, SMEM_TC);

    // prep + operand 3-plane expansion
    prep_kernel<<<(G6 * KCAT) / 256, 256>>>(w_l, w_r, b_l, b_r);
    expand_kernel<<<(int)((PS_F  + 255) / 256), 256>>>(features, Fe,  PS_F,  (int)PS_F);
    expand_kernel<<<(int)((PS_WX + 255) / 256), 256>>>(w_iox,    Wxe, PS_WX, (int)PS_WX);
    expand_kernel<<<(int)((PS_WP + 255) / 256), 256>>>(w_px,     Wpe, PS_WP, (int)PS_WP);
    expand_kernel<<<(int)((PS_WC + 255) / 256), 256>>>(Wcat,     Wce, PS_WC, (int)PS_WC);

    // phase A: x-gates and px
    gemm_bf<<<dim3(G6 / 128,   N_OBJ / 128), 256, SMEM_TC>>>(Fe, PS_F, Wxe, PS_WX, b_iox, XG, N_OBJ, G6);
    gemm_bf<<<dim3(HDIM / 128, N_OBJ / 128), 256, SMEM_TC>>>(Fe, PS_F, Wpe, PS_WP, b_px,  PX, N_OBJ, HDIM);

    // leaves
    pointwise<<<(1024 * HDIM + 255) / 256, 256>>>(1024, 1024, nullptr);

    // node 1023 (single, fp32 path; children rows 2047 + sentinel 2048)
    gemm_small<<<G6 / 8, 256>>>(Htab + (size_t)2047 * HDIM, Wcat, Gh, 1, G6, KCAT);
    pointwise<<<(1 * HDIM + 255) / 256, 256>>>(1023, 1, Gh);

    // big internal wavefronts (M padded to 128 where needed; A rows in-bounds)
    struct Lv { int s, M; };
    const Lv big[5] = { {511, 512}, {255, 256}, {127, 128}, {63, 64}, {31, 32} };
    for (int li = 0; li < 5; li++) {
        int s = big[li].s, M = big[li].M;
        int Mtiles = (M + 127) / 128;
        const __nv_bfloat16* Ab = He + (size_t)(2 * s + 1) * HDIM;
        gemm_bf<<<dim3(G6 / 128, Mtiles), 256, SMEM_TC>>>(Ab, PS_H, Wce, PS_WC, nullptr, Gh, M, G6);
        pointwise<<<(M * HDIM + 255) / 256, 256>>>(s, M, Gh);
    }

    // tiny wavefronts (fp32 warp-dot)
    const Lv small_[5] = { {15, 16}, {7, 8}, {3, 4}, {1, 2}, {0, 1} };
    for (int li = 0; li < 5; li++) {
        int s = small_[li].s, M = small_[li].M;
        gemm_small<<<G6 / 8, 256>>>(Htab + (size_t)(2 * s + 1) * HDIM, Wcat, Gh, M, G6, KCAT);
        pointwise<<<(M * HDIM + 255) / 256, 256>>>(s, M, Gh);
    }

    copyout<<<(N_OBJ * HDIM / 4) / 256, 256>>>((float*)d_out);
}

// round 7
// speedup vs baseline: 1.7738x; 1.3825x over previous
#include <cuda_runtime.h>
#include <cuda_bf16.h>
#include <math.h>
#include <stdint.h>

#define N_OBJ 2048
#define FDIM  2048
#define HDIM  1024
#define G6    6144          // 6*HDIM
#define KCAT  2048          // 2*HDIM
#define NCH   256           // 4 terms * (2048/32) k-chunks

// plane strides (elements)
#define PS_F  ((size_t)N_OBJ * FDIM)
#define PS_WX ((size_t)G6 * FDIM)
#define PS_WP ((size_t)HDIM * FDIM)
#define PS_WC ((size_t)G6 * KCAT)
#define PS_H  ((size_t)(N_OBJ + 1) * HDIM)

// 4-term expansion: (a0+a1)(b0+b1) -> terms (ta,tb) = (0,0),(0,1),(1,0),(1,1)
#define TA_PACK 0x1100u
#define TB_PACK 0x1010u

// ---------------- scratch (static device globals; no allocation) -------------
__device__ float g_XG[(size_t)N_OBJ * G6];
__device__ float g_PX[(size_t)N_OBJ * HDIM];
__device__ float g_Wcat[(size_t)G6 * KCAT];          // fp32 (tiny-M path)
__device__ float g_biaslr[G6];
__device__ float g_C[(size_t)(N_OBJ + 1) * HDIM];
__device__ float g_H[(size_t)(N_OBJ + 1) * HDIM];
__device__ float g_Gh[(size_t)512 * G6];

// bf16 split planes (2 planes each: hi, lo)
__device__ __nv_bfloat16 g_Fe [2 * PS_F];
__device__ __nv_bfloat16 g_Wxe[2 * PS_WX];
__device__ __nv_bfloat16 g_Wpe[2 * PS_WP];
__device__ __nv_bfloat16 g_Wce[2 * PS_WC];
__device__ __nv_bfloat16 g_He [2 * PS_H];

// ---------------- helpers ----------------------------------------------------
__device__ __forceinline__ uint32_t smem_to_u32(const void* p) {
    uint32_t a;
    asm("{ .reg .u64 t; cvta.to.shared.u64 t, %1; cvt.u32.u64 %0, t; }" : "=r"(a) : "l"(p));
    return a;
}
__device__ __forceinline__ void ldmx4(uint32_t* d, uint32_t addr) {
    asm volatile("ldmatrix.sync.aligned.m8n8.x4.shared.b16 {%0,%1,%2,%3}, [%4];"
                 : "=r"(d[0]), "=r"(d[1]), "=r"(d[2]), "=r"(d[3]) : "r"(addr));
}
__device__ __forceinline__ void mma_bf16(float* c, const uint32_t* a, const uint32_t* b) {
    asm volatile("mma.sync.aligned.m16n8k16.row.col.f32.bf16.bf16.f32 "
                 "{%0,%1,%2,%3}, {%4,%5,%6,%7}, {%8,%9}, {%0,%1,%2,%3};"
                 : "+f"(c[0]), "+f"(c[1]), "+f"(c[2]), "+f"(c[3])
                 : "r"(a[0]), "r"(a[1]), "r"(a[2]), "r"(a[3]), "r"(b[0]), "r"(b[1]));
}
__device__ __forceinline__ void cpasync16(uint32_t dst, const void* src) {
    asm volatile("cp.async.cg.shared.global [%0], [%1], 16;" :: "r"(dst), "l"(src));
}

// swizzle: 16B chunk x (0..3) within a 64B row r -> conflict-free for both
// cp.async stores and ldmatrix reads.
__device__ __forceinline__ uint32_t swz(int r, int x) {
    return (uint32_t)(r * 64 + ((x ^ ((r >> 1) & 3)) << 4));
}

// ---------------- bf16 double-split ------------------------------------------
__device__ __forceinline__ void bf16_split2(float x, __nv_bfloat16& t0, __nv_bfloat16& t1)
{
    t0 = __float2bfloat16(x);
    t1 = __float2bfloat16(x - __bfloat162float(t0));
}

// expand src fp32 [total] into 2 bf16 planes (hi, lo)
__global__ void expand_kernel(const float* __restrict__ src, __nv_bfloat16* __restrict__ dst,
                              size_t planeStride, int total)
{
    int i = blockIdx.x * 256 + threadIdx.x;
    if (i >= total) return;
    __nv_bfloat16 t0, t1;
    bf16_split2(src[i], t0, t1);
    dst[i] = t0;
    dst[planeStride + i] = t1;
}

// ---------------- prep: Wcat fp32, biaslr, sentinel rows ---------------------
__global__ void prep_kernel(const float* __restrict__ wl, const float* __restrict__ wr,
                            const float* __restrict__ bl, const float* __restrict__ br)
{
    int idx = blockIdx.x * 256 + threadIdx.x;   // over G6*KCAT
    int j = idx >> 11;
    int k = idx & (KCAT - 1);
    float w = (k < HDIM) ? wl[(size_t)j * HDIM + k] : wr[(size_t)j * HDIM + (k - HDIM)];
    g_Wcat[idx] = w;
    if (idx < G6) g_biaslr[idx] = bl[idx] + br[idx];
    if (idx < HDIM) {
        size_t s = (size_t)N_OBJ * HDIM + idx;
        g_C[s] = 0.f; g_H[s] = 0.f;
        __nv_bfloat16 z = __float2bfloat16(0.f);
        g_He[s] = z; g_He[PS_H + s] = z;
    }
}

// ---------------- bf16 mma GEMM: C = sum_t A[TA(t)] @ B[TB(t)]^T (+bias) -----
// A, B: 2 bf16 planes, row stride 2048 elems within each plane.
// BM=BN=128, BK=32, 4-stage cp.async pipeline, ldmatrix fragments.
// Grid is 2D (tiles_n, tiles_m) but remapped: supertiles of 8 n-tiles spanning
// all m-tiles, so one CTA wave's operand working set fits in L2.
__global__ __launch_bounds__(256, 2) void gemm_bf(
    const __nv_bfloat16* __restrict__ A, size_t psA,
    const __nv_bfloat16* __restrict__ B, size_t psB,
    const float* __restrict__ bias, float* __restrict__ C, int M, int N)
{
    extern __shared__ char smem[];
    const uint32_t sb = smem_to_u32(smem);
    const int tid = threadIdx.x, lane = tid & 31, warp = tid >> 5;
    const int wr_ = warp >> 2, wc_ = warp & 3;            // 2 x 4 warp grid

    // ---- L2-aware tile swizzle ----
    const int tiles_n = gridDim.x, tiles_m = gridDim.y;
    int lid = blockIdx.y * tiles_n + blockIdx.x;
    const int GRP = 8;                                    // n-tiles per group
    int per_group = GRP * tiles_m;
    int grp = lid / per_group, rem = lid - grp * per_group;
    int nt0 = grp * GRP;
    int gn = tiles_n - nt0; if (gn > GRP) gn = GRP;
    int nt = nt0 + rem % gn;
    int mt = rem / gn;
    const int row0 = mt * 128, col0 = nt * 128;

    // ldmatrix lane geometry
    const int lrow = ((lane >> 3) & 1) * 8 + (lane & 7);  // row within 16
    const int lcol = lane >> 4;                           // 0/1 -> k 16B chunk

    // cp.async op coords (ops o = tid and tid+256; r = o>>2, ch = o&3)
    const int r_op0 = tid >> 2,         ch0 = tid & 3;
    const int r_op1 = (tid + 256) >> 2, ch1 = tid & 3;

    float acc[4][4][4];
#pragma unroll
    for (int a = 0; a < 4; a++)
#pragma unroll
        for (int b = 0; b < 4; b++)
#pragma unroll
            for (int t = 0; t < 4; t++) acc[a][b][t] = 0.f;

    auto load_chunk = [&](int c, int st) {
        int t = c >> 6;
        size_t pa = (size_t)((TA_PACK >> (4 * t)) & 0xF) * psA;
        size_t pb = (size_t)((TB_PACK >> (4 * t)) & 0xF) * psB;
        const __nv_bfloat16* Ab = A + pa + (size_t)(c & 63) * 32;
        const __nv_bfloat16* Bb = B + pb + (size_t)(c & 63) * 32;
        uint32_t sA = sb + st * 16384, sBm = sA + 8192;
        cpasync16(sA  + swz(r_op0, ch0), Ab + (size_t)(row0 + r_op0) * 2048 + ch0 * 8);
        cpasync16(sA  + swz(r_op1, ch1), Ab + (size_t)(row0 + r_op1) * 2048 + ch1 * 8);
        cpasync16(sBm + swz(r_op0, ch0), Bb + (size_t)(col0 + r_op0) * 2048 + ch0 * 8);
        cpasync16(sBm + swz(r_op1, ch1), Bb + (size_t)(col0 + r_op1) * 2048 + ch1 * 8);
        asm volatile("cp.async.commit_group;" ::: "memory");
    };

    load_chunk(0, 0); load_chunk(1, 1); load_chunk(2, 2);

    for (int c = 0; c < NCH; c++) {
        int st = c & 3;
        if (c + 3 < NCH) {
            asm volatile("cp.async.wait_group 2;" ::: "memory");
        } else {
            asm volatile("cp.async.wait_group 0;" ::: "memory");   // tail drain
        }
        __syncthreads();
        if (c + 3 < NCH) load_chunk(c + 3, (c + 3) & 3);

        uint32_t sA = sb + st * 16384, sBm = sA + 8192;
#pragma unroll
        for (int kk = 0; kk < 2; kk++) {                  // two k16 steps
            uint32_t af[4][4], bq[2][4];
#pragma unroll
            for (int mf = 0; mf < 4; mf++) {
                int r = wr_ * 64 + mf * 16 + lrow;
                ldmx4(af[mf], sA + swz(r, lcol + kk * 2));
            }
#pragma unroll
            for (int bh = 0; bh < 2; bh++) {
                int r = wc_ * 32 + bh * 16 + lrow;
                ldmx4(bq[bh], sBm + swz(r, lcol + kk * 2));
            }
#pragma unroll
            for (int mf = 0; mf < 4; mf++)
#pragma unroll
                for (int nf = 0; nf < 4; nf++) {
                    uint32_t b2[2] = { bq[nf >> 1][nf & 1], bq[nf >> 1][2 + (nf & 1)] };
                    mma_bf16(acc[mf][nf], af[mf], b2);
                }
        }
    }

    // ---- epilogue ----
#pragma unroll
    for (int mf = 0; mf < 4; mf++) {
#pragma unroll
        for (int nf = 0; nf < 4; nf++) {
            int r  = row0 + wr_ * 64 + mf * 16 + (lane >> 2);
            int cb = col0 + wc_ * 32 + nf * 8 + (lane & 3) * 2;
            float b0 = bias ? bias[cb] : 0.f;
            float b1 = bias ? bias[cb + 1] : 0.f;
            if (r < M) {
                C[(size_t)r * N + cb]     = acc[mf][nf][0] + b0;
                C[(size_t)r * N + cb + 1] = acc[mf][nf][1] + b1;
            }
            if (r + 8 < M) {
                C[(size_t)(r + 8) * N + cb]     = acc[mf][nf][2] + b0;
                C[(size_t)(r + 8) * N + cb + 1] = acc[mf][nf][3] + b1;
            }
        }
    }
}

// ---------------- tiny-M GEMM (M<=16): one warp per output column n ---------
__global__ void gemm_small(const float* __restrict__ A, const float* __restrict__ B,
                           float* __restrict__ C, int M, int N, int K)
{
    int warp = threadIdx.x >> 5, lane = threadIdx.x & 31;
    int n = blockIdx.x * 8 + warp;
    if (n >= N) return;
    float acc[16];
#pragma unroll
    for (int m = 0; m < 16; m++) acc[m] = 0.f;
    const float* Brow = B + (size_t)n * K;
    for (int k = lane * 4; k < K; k += 128) {
        float4 bv = *(const float4*)(Brow + k);
#pragma unroll
        for (int m = 0; m < 16; m++) {
            if (m < M) {
                float4 av = *(const float4*)(A + (size_t)m * K + k);
                acc[m] += av.x * bv.x + av.y * bv.y + av.z * bv.z + av.w * bv.w;
            }
        }
    }
#pragma unroll
    for (int m = 0; m < 16; m++) {
        if (m < M) {
            float v = acc[m];
#pragma unroll
            for (int off = 16; off; off >>= 1) v += __shfl_xor_sync(~0u, v, off);
            if (lane == 0) C[(size_t)m * N + n] = v;
        }
    }
}

// ---------------- pointwise LSTM cell for one wavefront ----------------------
__device__ __forceinline__ float sigm(float x) { return 1.f / (1.f + expf(-x)); }

__global__ void pointwise(int s, int M, const float* __restrict__ Gh)
{
    int idx = blockIdx.x * blockDim.x + threadIdx.x;
    if (idx >= M * HDIM) return;
    int m = idx >> 10;
    int j = idx & (HDIM - 1);
    int n = s + m;

    const float* xg = g_XG + (size_t)n * G6;
    const float* gh = Gh ? (Gh + (size_t)m * G6) : nullptr;
    float g[6];
#pragma unroll
    for (int t = 0; t < 6; t++) {
        int o = t * HDIM + j;
        g[t] = xg[o] + g_biaslr[o] + (gh ? gh[o] : 0.f);
    }
    float ig = sigm(g[0]), og = sigm(g[1]);
    float fl = sigm(g[2]), fr = sigm(g[3]);
    float u  = tanhf(g[4]), rr = sigm(g[5]);

    int l = 2 * n + 1; if (l > N_OBJ) l = N_OBJ;
    int r = 2 * n + 2; if (r > N_OBJ) r = N_OBJ;

    float c = ig * u + fl * g_C[(size_t)l * HDIM + j] + fr * g_C[(size_t)r * HDIM + j];
    float h = og * tanhf(c);
    float hf = rr * h + (1.f - rr) * g_PX[(size_t)n * HDIM + j];

    size_t o = (size_t)n * HDIM + j;
    g_C[o] = c;
    g_H[o] = hf;
    __nv_bfloat16 t0, t1;
    bf16_split2(hf, t0, t1);
    g_He[o] = t0; g_He[PS_H + o] = t1;
}

// ---------------- final copy -------------------------------------------------
__global__ void copyout(float* __restrict__ out)
{
    int idx = blockIdx.x * 256 + threadIdx.x;
    ((float4*)out)[idx] = ((const float4*)g_H)[idx];
}

// ---------------- launcher ---------------------------------------------------
extern "C" void kernel_launch(void* const* d_in, const int* in_sizes, int n_in,
                              void* d_out, int out_size)
{
    const float* features = (const float*)d_in[0];
    const float* w_iox    = (const float*)d_in[1];
    const float* b_iox    = (const float*)d_in[2];
    const float* w_l      = (const float*)d_in[3];
    const float* b_l      = (const float*)d_in[4];
    const float* w_r      = (const float*)d_in[5];
    const float* b_r      = (const float*)d_in[6];
    const float* w_px     = (const float*)d_in[7];
    const float* b_px     = (const float*)d_in[8];

    float *XG, *PX, *Wcat, *Gh, *Htab;
    __nv_bfloat16 *Fe, *Wxe, *Wpe, *Wce, *He;
    cudaGetSymbolAddress((void**)&XG,   g_XG);
    cudaGetSymbolAddress((void**)&PX,   g_PX);
    cudaGetSymbolAddress((void**)&Wcat, g_Wcat);
    cudaGetSymbolAddress((void**)&Gh,   g_Gh);
    cudaGetSymbolAddress((void**)&Htab, g_H);
    cudaGetSymbolAddress((void**)&Fe,   g_Fe);
    cudaGetSymbolAddress((void**)&Wxe,  g_Wxe);
    cudaGetSymbolAddress((void**)&Wpe,  g_Wpe);
    cudaGetSymbolAddress((void**)&Wce,  g_Wce);
    cudaGetSymbolAddress((void**)&He,   g_He);

    const int SMEM_TC = 4 * 16384;
    cudaFuncSetAttribute(gemm_bf, cudaFuncAttributeMaxDynamicSharedMemorySize, SMEM_TC);

    // prep + operand 2-plane expansion
    prep_kernel<<<(G6 * KCAT) / 256, 256>>>(w_l, w_r, b_l, b_r);
    expand_kernel<<<(int)((PS_F  + 255) / 256), 256>>>(features, Fe,  PS_F,  (int)PS_F);
    expand_kernel<<<(int)((PS_WX + 255) / 256), 256>>>(w_iox,    Wxe, PS_WX, (int)PS_WX);
    expand_kernel<<<(int)((PS_WP + 255) / 256), 256>>>(w_px,     Wpe, PS_WP, (int)PS_WP);
    expand_kernel<<<(int)((PS_WC + 255) / 256), 256>>>(Wcat,     Wce, PS_WC, (int)PS_WC);

    // phase A: x-gates and px
    gemm_bf<<<dim3(G6 / 128,   N_OBJ / 128), 256, SMEM_TC>>>(Fe, PS_F, Wxe, PS_WX, b_iox, XG, N_OBJ, G6);
    gemm_bf<<<dim3(HDIM / 128, N_OBJ / 128), 256, SMEM_TC>>>(Fe, PS_F, Wpe, PS_WP, b_px,  PX, N_OBJ, HDIM);

    // leaves
    pointwise<<<(1024 * HDIM + 255) / 256, 256>>>(1024, 1024, nullptr);

    // node 1023 (single, fp32 path; children rows 2047 + sentinel 2048)
    gemm_small<<<G6 / 8, 256>>>(Htab + (size_t)2047 * HDIM, Wcat, Gh, 1, G6, KCAT);
    pointwise<<<(1 * HDIM + 255) / 256, 256>>>(1023, 1, Gh);

    // big internal wavefronts (M padded to 128 where needed; A rows in-bounds)
    struct Lv { int s, M; };
    const Lv big[5] = { {511, 512}, {255, 256}, {127, 128}, {63, 64}, {31, 32} };
    for (int li = 0; li < 5; li++) {
        int s = big[li].s, M = big[li].M;
        int Mtiles = (M + 127) / 128;
        const __nv_bfloat16* Ab = He + (size_t)(2 * s + 1) * HDIM;
        gemm_bf<<<dim3(G6 / 128, Mtiles), 256, SMEM_TC>>>(Ab, PS_H, Wce, PS_WC, nullptr, Gh, M, G6);
        pointwise<<<(M * HDIM + 255) / 256, 256>>>(s, M, Gh);
    }

    // tiny wavefronts (fp32 warp-dot)
    const Lv small_[5] = { {15, 16}, {7, 8}, {3, 4}, {1, 2}, {0, 1} };
    for (int li = 0; li < 5; li++) {
        int s = small_[li].s, M = small_[li].M;
        gemm_small<<<G6 / 8, 256>>>(Htab + (size_t)(2 * s + 1) * HDIM, Wcat, Gh, M, G6, KCAT);
        pointwise<<<(M * HDIM + 255) / 256, 256>>>(s, M, Gh);
    }

    copyout<<<(N_OBJ * HDIM / 4) / 256, 256>>>((float*)d_out);
}

// round 8
// speedup vs baseline: 2.6920x; 1.5177x over previous
#include <cuda_runtime.h>
#include <cuda_bf16.h>
#include <math.h>
#include <stdint.h>

#define N_OBJ 2048
#define FDIM  2048
#define HDIM  1024
#define G6    6144          // 6*HDIM
#define KCAT  2048          // 2*HDIM
#define NCH   192           // 3 terms * (2048/32) k-chunks

// plane strides (elements)
#define PS_F  ((size_t)N_OBJ * FDIM)
#define PS_WX ((size_t)G6 * FDIM)
#define PS_WP ((size_t)HDIM * FDIM)
#define PS_WC ((size_t)G6 * KCAT)
#define PS_H  ((size_t)(N_OBJ + 1) * HDIM)

// 3-term expansion: a0b0 + a0b1 + a1b0  (a1b1 dropped, ~2^-18 relative)
#define TA_PACK 0x100u      // TA = {0,0,1}
#define TB_PACK 0x010u      // TB = {0,1,0}

// ---------------- scratch (static device globals; no allocation) -------------
__device__ float g_XG[(size_t)N_OBJ * G6];
__device__ float g_PX[(size_t)N_OBJ * HDIM];
__device__ float g_Wcat[(size_t)G6 * KCAT];          // fp32 (tiny-M path)
__device__ float g_biaslr[G6];
__device__ float g_C[(size_t)(N_OBJ + 1) * HDIM];
__device__ float g_H[(size_t)(N_OBJ + 1) * HDIM];
__device__ float g_Gh[(size_t)1024 * G6];            // split-K partial slabs

// bf16 split planes (2 planes each: hi, lo)
__device__ __nv_bfloat16 g_Fe [2 * PS_F];
__device__ __nv_bfloat16 g_Wxe[2 * PS_WX];
__device__ __nv_bfloat16 g_Wpe[2 * PS_WP];
__device__ __nv_bfloat16 g_Wce[2 * PS_WC];
__device__ __nv_bfloat16 g_He [2 * PS_H];

// ---------------- helpers ----------------------------------------------------
__device__ __forceinline__ uint32_t smem_to_u32(const void* p) {
    uint32_t a;
    asm("{ .reg .u64 t; cvta.to.shared.u64 t, %1; cvt.u32.u64 %0, t; }" : "=r"(a) : "l"(p));
    return a;
}
__device__ __forceinline__ void ldmx4(uint32_t* d, uint32_t addr) {
    asm volatile("ldmatrix.sync.aligned.m8n8.x4.shared.b16 {%0,%1,%2,%3}, [%4];"
                 : "=r"(d[0]), "=r"(d[1]), "=r"(d[2]), "=r"(d[3]) : "r"(addr));
}
__device__ __forceinline__ void mma_bf16(float* c, const uint32_t* a, const uint32_t* b) {
    asm volatile("mma.sync.aligned.m16n8k16.row.col.f32.bf16.bf16.f32 "
                 "{%0,%1,%2,%3}, {%4,%5,%6,%7}, {%8,%9}, {%0,%1,%2,%3};"
                 : "+f"(c[0]), "+f"(c[1]), "+f"(c[2]), "+f"(c[3])
                 : "r"(a[0]), "r"(a[1]), "r"(a[2]), "r"(a[3]), "r"(b[0]), "r"(b[1]));
}
__device__ __forceinline__ void cpasync16(uint32_t dst, const void* src) {
    asm volatile("cp.async.cg.shared.global [%0], [%1], 16;" :: "r"(dst), "l"(src));
}

// swizzle: 16B chunk x (0..3) within a 64B row r -> conflict-free for both
// cp.async stores and ldmatrix reads.
__device__ __forceinline__ uint32_t swz(int r, int x) {
    return (uint32_t)(r * 64 + ((x ^ ((r >> 1) & 3)) << 4));
}

// ---------------- bf16 double-split ------------------------------------------
__device__ __forceinline__ void bf16_split2(float x, __nv_bfloat16& t0, __nv_bfloat16& t1)
{
    t0 = __float2bfloat16(x);
    t1 = __float2bfloat16(x - __bfloat162float(t0));
}

// expand src fp32 [total] into 2 bf16 planes (hi, lo)
__global__ void expand_kernel(const float* __restrict__ src, __nv_bfloat16* __restrict__ dst,
                              size_t planeStride, int total)
{
    int i = blockIdx.x * 256 + threadIdx.x;
    if (i >= total) return;
    __nv_bfloat16 t0, t1;
    bf16_split2(src[i], t0, t1);
    dst[i] = t0;
    dst[planeStride + i] = t1;
}

// ---------------- prep: Wcat fp32, biaslr, sentinel rows ---------------------
__global__ void prep_kernel(const float* __restrict__ wl, const float* __restrict__ wr,
                            const float* __restrict__ bl, const float* __restrict__ br)
{
    int idx = blockIdx.x * 256 + threadIdx.x;   // over G6*KCAT
    int j = idx >> 11;
    int k = idx & (KCAT - 1);
    float w = (k < HDIM) ? wl[(size_t)j * HDIM + k] : wr[(size_t)j * HDIM + (k - HDIM)];
    g_Wcat[idx] = w;
    if (idx < G6) g_biaslr[idx] = bl[idx] + br[idx];
    if (idx < HDIM) {
        size_t s = (size_t)N_OBJ * HDIM + idx;
        g_C[s] = 0.f; g_H[s] = 0.f;
        __nv_bfloat16 z = __float2bfloat16(0.f);
        g_He[s] = z; g_He[PS_H + s] = z;
    }
}

// ---------------- bf16 mma GEMM: C = sum_t A[TA(t)] @ B[TB(t)]^T (+bias) -----
// A, B: 2 bf16 planes, row stride 2048 elems within each plane.
// BM=BN=128, BK=32, 4-stage cp.async pipeline, ldmatrix fragments.
// Split-K: blockIdx.z = part; part p handles chunks [p*cpp, (p+1)*cpp) and
// writes its own output slab C + p*M*N. Deterministic (no atomics).
__global__ __launch_bounds__(256, 2) void gemm_bf(
    const __nv_bfloat16* __restrict__ A, size_t psA,
    const __nv_bfloat16* __restrict__ B, size_t psB,
    const float* __restrict__ bias, float* __restrict__ C, int M, int N, int cpp)
{
    extern __shared__ char smem[];
    const uint32_t sb = smem_to_u32(smem);
    const int tid = threadIdx.x, lane = tid & 31, warp = tid >> 5;
    const int wr_ = warp >> 2, wc_ = warp & 3;            // 2 x 4 warp grid

    const int part = blockIdx.z;
    C += (size_t)part * M * N;
    const int c0 = part * cpp;

    // ---- L2-aware tile swizzle (within a part) ----
    const int tiles_n = gridDim.x, tiles_m = gridDim.y;
    int lid = blockIdx.y * tiles_n + blockIdx.x;
    const int GRP = 8;
    int per_group = GRP * tiles_m;
    int grp = lid / per_group, rem = lid - grp * per_group;
    int nt0 = grp * GRP;
    int gn = tiles_n - nt0; if (gn > GRP) gn = GRP;
    int nt = nt0 + rem % gn;
    int mt = rem / gn;
    const int row0 = mt * 128, col0 = nt * 128;

    // ldmatrix lane geometry
    const int lrow = ((lane >> 3) & 1) * 8 + (lane & 7);
    const int lcol = lane >> 4;

    // cp.async op coords
    const int r_op0 = tid >> 2,         ch0 = tid & 3;
    const int r_op1 = (tid + 256) >> 2, ch1 = tid & 3;

    float acc[4][4][4];
#pragma unroll
    for (int a = 0; a < 4; a++)
#pragma unroll
        for (int b = 0; b < 4; b++)
#pragma unroll
            for (int t = 0; t < 4; t++) acc[a][b][t] = 0.f;

    auto load_chunk = [&](int c, int st) {
        int t = c >> 6;
        size_t pa = (size_t)((TA_PACK >> (4 * t)) & 0xF) * psA;
        size_t pb = (size_t)((TB_PACK >> (4 * t)) & 0xF) * psB;
        const __nv_bfloat16* Ab = A + pa + (size_t)(c & 63) * 32;
        const __nv_bfloat16* Bb = B + pb + (size_t)(c & 63) * 32;
        uint32_t sA = sb + st * 16384, sBm = sA + 8192;
        cpasync16(sA  + swz(r_op0, ch0), Ab + (size_t)(row0 + r_op0) * 2048 + ch0 * 8);
        cpasync16(sA  + swz(r_op1, ch1), Ab + (size_t)(row0 + r_op1) * 2048 + ch1 * 8);
        cpasync16(sBm + swz(r_op0, ch0), Bb + (size_t)(col0 + r_op0) * 2048 + ch0 * 8);
        cpasync16(sBm + swz(r_op1, ch1), Bb + (size_t)(col0 + r_op1) * 2048 + ch1 * 8);
        asm volatile("cp.async.commit_group;" ::: "memory");
    };

    load_chunk(c0, 0); load_chunk(c0 + 1, 1); load_chunk(c0 + 2, 2);

    for (int i = 0; i < cpp; i++) {
        int st = i & 3;
        if (i + 3 < cpp) {
            asm volatile("cp.async.wait_group 2;" ::: "memory");
        } else {
            asm volatile("cp.async.wait_group 0;" ::: "memory");   // tail drain
        }
        __syncthreads();
        if (i + 3 < cpp) load_chunk(c0 + i + 3, (i + 3) & 3);

        uint32_t sA = sb + st * 16384, sBm = sA + 8192;
#pragma unroll
        for (int kk = 0; kk < 2; kk++) {
            uint32_t af[4][4], bq[2][4];
#pragma unroll
            for (int mf = 0; mf < 4; mf++) {
                int r = wr_ * 64 + mf * 16 + lrow;
                ldmx4(af[mf], sA + swz(r, lcol + kk * 2));
            }
#pragma unroll
            for (int bh = 0; bh < 2; bh++) {
                int r = wc_ * 32 + bh * 16 + lrow;
                ldmx4(bq[bh], sBm + swz(r, lcol + kk * 2));
            }
#pragma unroll
            for (int mf = 0; mf < 4; mf++)
#pragma unroll
                for (int nf = 0; nf < 4; nf++) {
                    uint32_t b2[2] = { bq[nf >> 1][nf & 1], bq[nf >> 1][2 + (nf & 1)] };
                    mma_bf16(acc[mf][nf], af[mf], b2);
                }
        }
    }

    // ---- epilogue ----
#pragma unroll
    for (int mf = 0; mf < 4; mf++) {
#pragma unroll
        for (int nf = 0; nf < 4; nf++) {
            int r  = row0 + wr_ * 64 + mf * 16 + (lane >> 2);
            int cb = col0 + wc_ * 32 + nf * 8 + (lane & 3) * 2;
            float b0 = bias ? bias[cb] : 0.f;
            float b1 = bias ? bias[cb + 1] : 0.f;
            if (r < M) {
                C[(size_t)r * N + cb]     = acc[mf][nf][0] + b0;
                C[(size_t)r * N + cb + 1] = acc[mf][nf][1] + b1;
            }
            if (r + 8 < M) {
                C[(size_t)(r + 8) * N + cb]     = acc[mf][nf][2] + b0;
                C[(size_t)(r + 8) * N + cb + 1] = acc[mf][nf][3] + b1;
            }
        }
    }
}

// ---------------- tiny-M GEMM (M<=16): one warp per output column n ---------
__global__ void gemm_small(const float* __restrict__ A, const float* __restrict__ B,
                           float* __restrict__ C, int M, int N, int K)
{
    int warp = threadIdx.x >> 5, lane = threadIdx.x & 31;
    int n = blockIdx.x * 8 + warp;
    if (n >= N) return;
    float acc[16];
#pragma unroll
    for (int m = 0; m < 16; m++) acc[m] = 0.f;
    const float* Brow = B + (size_t)n * K;
    for (int k = lane * 4; k < K; k += 128) {
        float4 bv = *(const float4*)(Brow + k);
#pragma unroll
        for (int m = 0; m < 16; m++) {
            if (m < M) {
                float4 av = *(const float4*)(A + (size_t)m * K + k);
                acc[m] += av.x * bv.x + av.y * bv.y + av.z * bv.z + av.w * bv.w;
            }
        }
    }
#pragma unroll
    for (int m = 0; m < 16; m++) {
        if (m < M) {
            float v = acc[m];
#pragma unroll
            for (int off = 16; off; off >>= 1) v += __shfl_xor_sync(~0u, v, off);
            if (lane == 0) C[(size_t)m * N + n] = v;
        }
    }
}

// ---------------- pointwise LSTM cell for one wavefront ----------------------
__device__ __forceinline__ float sigm(float x) { return 1.f / (1.f + expf(-x)); }

__global__ void pointwise(int s, int M, const float* __restrict__ Gh,
                          int nparts, int pstride)
{
    int idx = blockIdx.x * blockDim.x + threadIdx.x;
    if (idx >= M * HDIM) return;
    int m = idx >> 10;
    int j = idx & (HDIM - 1);
    int n = s + m;

    const float* xg = g_XG + (size_t)n * G6;
    float g[6];
#pragma unroll
    for (int t = 0; t < 6; t++) {
        int o = t * HDIM + j;
        float v = xg[o] + g_biaslr[o];
        for (int p = 0; p < nparts; p++)
            v += Gh[(size_t)p * pstride + (size_t)m * G6 + o];
        g[t] = v;
    }
    float ig = sigm(g[0]), og = sigm(g[1]);
    float fl = sigm(g[2]), fr = sigm(g[3]);
    float u  = tanhf(g[4]), rr = sigm(g[5]);

    int l = 2 * n + 1; if (l > N_OBJ) l = N_OBJ;
    int r = 2 * n + 2; if (r > N_OBJ) r = N_OBJ;

    float c = ig * u + fl * g_C[(size_t)l * HDIM + j] + fr * g_C[(size_t)r * HDIM + j];
    float h = og * tanhf(c);
    float hf = rr * h + (1.f - rr) * g_PX[(size_t)n * HDIM + j];

    size_t o = (size_t)n * HDIM + j;
    g_C[o] = c;
    g_H[o] = hf;
    __nv_bfloat16 t0, t1;
    bf16_split2(hf, t0, t1);
    g_He[o] = t0; g_He[PS_H + o] = t1;
}

// ---------------- final copy -------------------------------------------------
__global__ void copyout(float* __restrict__ out)
{
    int idx = blockIdx.x * 256 + threadIdx.x;
    ((float4*)out)[idx] = ((const float4*)g_H)[idx];
}

// ---------------- launcher ---------------------------------------------------
extern "C" void kernel_launch(void* const* d_in, const int* in_sizes, int n_in,
                              void* d_out, int out_size)
{
    const float* features = (const float*)d_in[0];
    const float* w_iox    = (const float*)d_in[1];
    const float* b_iox    = (const float*)d_in[2];
    const float* w_l      = (const float*)d_in[3];
    const float* b_l      = (const float*)d_in[4];
    const float* w_r      = (const float*)d_in[5];
    const float* b_r      = (const float*)d_in[6];
    const float* w_px     = (const float*)d_in[7];
    const float* b_px     = (const float*)d_in[8];

    float *XG, *PX, *Wcat, *Gh, *Htab;
    __nv_bfloat16 *Fe, *Wxe, *Wpe, *Wce, *He;
    cudaGetSymbolAddress((void**)&XG,   g_XG);
    cudaGetSymbolAddress((void**)&PX,   g_PX);
    cudaGetSymbolAddress((void**)&Wcat, g_Wcat);
    cudaGetSymbolAddress((void**)&Gh,   g_Gh);
    cudaGetSymbolAddress((void**)&Htab, g_H);
    cudaGetSymbolAddress((void**)&Fe,   g_Fe);
    cudaGetSymbolAddress((void**)&Wxe,  g_Wxe);
    cudaGetSymbolAddress((void**)&Wpe,  g_Wpe);
    cudaGetSymbolAddress((void**)&Wce,  g_Wce);
    cudaGetSymbolAddress((void**)&He,   g_He);

    const int SMEM_TC = 4 * 16384;
    cudaFuncSetAttribute(gemm_bf, cudaFuncAttributeMaxDynamicSharedMemorySize, SMEM_TC);

    // prep + operand 2-plane expansion
    prep_kernel<<<(G6 * KCAT) / 256, 256>>>(w_l, w_r, b_l, b_r);
    expand_kernel<<<(int)((PS_F  + 255) / 256), 256>>>(features, Fe,  PS_F,  (int)PS_F);
    expand_kernel<<<(int)((PS_WX + 255) / 256), 256>>>(w_iox,    Wxe, PS_WX, (int)PS_WX);
    expand_kernel<<<(int)((PS_WP + 255) / 256), 256>>>(w_px,     Wpe, PS_WP, (int)PS_WP);
    expand_kernel<<<(int)((PS_WC + 255) / 256), 256>>>(Wcat,     Wce, PS_WC, (int)PS_WC);

    // phase A: x-gates and px (no split-K; full-chip grids)
    gemm_bf<<<dim3(G6 / 128,   N_OBJ / 128, 1), 256, SMEM_TC>>>(Fe, PS_F, Wxe, PS_WX, b_iox, XG, N_OBJ, G6,   NCH);
    gemm_bf<<<dim3(HDIM / 128, N_OBJ / 128, 1), 256, SMEM_TC>>>(Fe, PS_F, Wpe, PS_WP, b_px,  PX, N_OBJ, HDIM, NCH);

    // leaves
    pointwise<<<(1024 * HDIM + 255) / 256, 256>>>(1024, 1024, nullptr, 0, 0);

    // node 1023 (single, fp32 path; children rows 2047 + sentinel 2048)
    gemm_small<<<G6 / 8, 256>>>(Htab + (size_t)2047 * HDIM, Wcat, Gh, 1, G6, KCAT);
    pointwise<<<(1 * HDIM + 255) / 256, 256>>>(1023, 1, Gh, 1, 0);

    // big internal wavefronts with deterministic split-K
    struct Lv { int s, M, KS; };
    const Lv big[5] = { {511, 512, 2}, {255, 256, 4}, {127, 128, 8},
                        {63, 64, 8}, {31, 32, 8} };
    for (int li = 0; li < 5; li++) {
        int s = big[li].s, M = big[li].M, KS = big[li].KS;
        int Mtiles = (M + 127) / 128;
        const __nv_bfloat16* Ab = He + (size_t)(2 * s + 1) * HDIM;
        gemm_bf<<<dim3(G6 / 128, Mtiles, KS), 256, SMEM_TC>>>(
            Ab, PS_H, Wce, PS_WC, nullptr, Gh, M, G6, NCH / KS);
        pointwise<<<(M * HDIM + 255) / 256, 256>>>(s, M, Gh, KS, M * G6);
    }

    // tiny wavefronts (fp32 warp-dot)
    const Lv small_[5] = { {15, 16, 0}, {7, 8, 0}, {3, 4, 0}, {1, 2, 0}, {0, 1, 0} };
    for (int li = 0; li < 5; li++) {
        int s = small_[li].s, M = small_[li].M;
        gemm_small<<<G6 / 8, 256>>>(Htab + (size_t)(2 * s + 1) * HDIM, Wcat, Gh, M, G6, KCAT);
        pointwise<<<(M * HDIM + 255) / 256, 256>>>(s, M, Gh, 1, 0);
    }

    copyout<<<(N_OBJ * HDIM / 4) / 256, 256>>>((float*)d_out);
}